// round 2
// baseline (speedup 1.0000x reference)
#include <cuda_runtime.h>

#define NN 40000
#define EE 640000
#define DIM 128
#define NB 157   // ceil(40000/256)

// Scratch (static device globals — no allocation)
__device__ float g_hs[NN * DIM];   // (h_in @ W) * dinv[row]
__device__ float g_h[NN * DIM];    // layer output
__device__ float g_dinv[NN];
__device__ int   g_cnt[NN];
__device__ int   g_off[NN];
__device__ int   g_pos[NN];
__device__ int   g_ssrc[EE];       // edge srcs sorted by dst (CSR)
__device__ int   g_bsum[NB];
__device__ int   g_bbase[NB];

// ---------------- degree / CSR build ----------------

__global__ void zero_k() {
    int i = blockIdx.x * blockDim.x + threadIdx.x;
    if (i < NN) g_cnt[i] = 0;
}

__global__ void count_k(const int* __restrict__ dst) {
    int e = blockIdx.x * blockDim.x + threadIdx.x;
    if (e < EE) atomicAdd(&g_cnt[dst[e]], 1);
}

__global__ void dinv_k() {
    int i = blockIdx.x * blockDim.x + threadIdx.x;
    if (i < NN) g_dinv[i] = rsqrtf(1.0f + (float)g_cnt[i]);
}

__global__ void scan1_k() {
    __shared__ int s[256];
    int i = blockIdx.x * 256 + threadIdx.x;
    s[threadIdx.x] = (i < NN) ? g_cnt[i] : 0;
    __syncthreads();
    for (int o = 128; o > 0; o >>= 1) {
        if (threadIdx.x < o) s[threadIdx.x] += s[threadIdx.x + o];
        __syncthreads();
    }
    if (threadIdx.x == 0) g_bsum[blockIdx.x] = s[0];
}

__global__ void scan2_k() {
    __shared__ int s[256];
    int t = threadIdx.x;
    int v = (t < NB) ? g_bsum[t] : 0;
    s[t] = v;
    __syncthreads();
    for (int o = 1; o < 256; o <<= 1) {
        int add = (t >= o) ? s[t - o] : 0;
        __syncthreads();
        s[t] += add;
        __syncthreads();
    }
    if (t < NB) g_bbase[t] = s[t] - v;   // exclusive base per chunk
}

__global__ void scan3_k() {
    __shared__ int s[256];
    int t = threadIdx.x;
    int i = blockIdx.x * 256 + t;
    int v = (i < NN) ? g_cnt[i] : 0;
    s[t] = v;
    __syncthreads();
    for (int o = 1; o < 256; o <<= 1) {
        int add = (t >= o) ? s[t - o] : 0;
        __syncthreads();
        s[t] += add;
        __syncthreads();
    }
    if (i < NN) {
        int off = g_bbase[blockIdx.x] + s[t] - v;  // exclusive prefix
        g_off[i] = off;
        g_pos[i] = off;
    }
}

__global__ void place_k(const int* __restrict__ src, const int* __restrict__ dst) {
    int e = blockIdx.x * blockDim.x + threadIdx.x;
    if (e < EE) {
        int d = dst[e];
        int p = atomicAdd(&g_pos[d], 1);
        g_ssrc[p] = src[e];
    }
}

// ---------------- GEMM: g_hs = (A @ W) * dinv[row] ----------------
// A: [NN,128] row-major (external x, or g_h when FROM_H), W: [128,128] row-major.
// Block: 256 threads -> 64x64 output tile; grid (625, 2). K tiled by 32.

template <bool FROM_H>
__global__ void gemm_k(const float* __restrict__ Ax, const float* __restrict__ W) {
    const float* __restrict__ A = FROM_H ? (const float*)g_h : Ax;
    __shared__ float As[64][36];   // stride 36 floats (conflict-safe, 16B-aligned)
    __shared__ float Bs[32][64];
    int tid = threadIdx.x;
    int tx = tid & 15, ty = tid >> 4;
    int r0 = blockIdx.x * 64;
    int c0 = blockIdx.y * 64;
    float acc[4][4] = {};

    for (int kt = 0; kt < 4; kt++) {
        #pragma unroll
        for (int t = tid; t < 512; t += 256) {
            int row = t >> 3, kk = (t & 7) << 2;
            float4 v = *(const float4*)&A[(r0 + row) * DIM + kt * 32 + kk];
            *(float4*)&As[row][kk] = v;
        }
        #pragma unroll
        for (int t = tid; t < 512; t += 256) {
            int k = t >> 4, cc = (t & 15) << 2;
            float4 v = *(const float4*)&W[(kt * 32 + k) * DIM + c0 + cc];
            *(float4*)&Bs[k][cc] = v;
        }
        __syncthreads();
        #pragma unroll
        for (int k = 0; k < 32; k++) {
            float a0 = As[ty * 4 + 0][k];
            float a1 = As[ty * 4 + 1][k];
            float a2 = As[ty * 4 + 2][k];
            float a3 = As[ty * 4 + 3][k];
            float4 b = *(const float4*)&Bs[k][tx * 4];
            acc[0][0] += a0 * b.x; acc[0][1] += a0 * b.y; acc[0][2] += a0 * b.z; acc[0][3] += a0 * b.w;
            acc[1][0] += a1 * b.x; acc[1][1] += a1 * b.y; acc[1][2] += a1 * b.z; acc[1][3] += a1 * b.w;
            acc[2][0] += a2 * b.x; acc[2][1] += a2 * b.y; acc[2][2] += a2 * b.z; acc[2][3] += a2 * b.w;
            acc[3][0] += a3 * b.x; acc[3][1] += a3 * b.y; acc[3][2] += a3 * b.z; acc[3][3] += a3 * b.w;
        }
        __syncthreads();
    }

    #pragma unroll
    for (int i = 0; i < 4; i++) {
        int row = r0 + ty * 4 + i;
        float d = g_dinv[row];
        float4 o;
        o.x = acc[i][0] * d; o.y = acc[i][1] * d;
        o.z = acc[i][2] * d; o.w = acc[i][3] * d;
        *(float4*)&g_hs[row * DIM + c0 + tx * 4] = o;
    }
}

// ---------------- Aggregation: one warp per node ----------------
// h_out[i] = relu(dinv[i] * (sum_{s in N(i)} hs[s] + hs[i]) + b)
// FINAL: also out[i] = h_out[i] . lin_w + lin_b

template <bool FINAL>
__global__ void agg_k(const float* __restrict__ bias,
                      const float* __restrict__ lw,
                      const float* __restrict__ lb,
                      float* __restrict__ out) {
    int w = (blockIdx.x * blockDim.x + threadIdx.x) >> 5;
    int lane = threadIdx.x & 31;
    if (w >= NN) return;
    int l4 = lane * 4;

    float4 acc = make_float4(0.f, 0.f, 0.f, 0.f);
    int beg = g_off[w];
    int n = g_cnt[w];
    #pragma unroll 4
    for (int e = beg; e < beg + n; e++) {
        int s = g_ssrc[e];
        float4 v = *(const float4*)&g_hs[s * DIM + l4];
        acc.x += v.x; acc.y += v.y; acc.z += v.z; acc.w += v.w;
    }
    float4 self = *(const float4*)&g_hs[w * DIM + l4];
    float di = g_dinv[w];
    float4 bb = *(const float4*)&bias[l4];

    float4 r;
    r.x = fmaxf(di * (acc.x + self.x) + bb.x, 0.f);
    r.y = fmaxf(di * (acc.y + self.y) + bb.y, 0.f);
    r.z = fmaxf(di * (acc.z + self.z) + bb.z, 0.f);
    r.w = fmaxf(di * (acc.w + self.w) + bb.w, 0.f);

    if (FINAL) {
        float4 lwv = *(const float4*)&lw[l4];
        float p = r.x * lwv.x + r.y * lwv.y + r.z * lwv.z + r.w * lwv.w;
        #pragma unroll
        for (int o = 16; o > 0; o >>= 1) p += __shfl_xor_sync(0xffffffffu, p, o);
        if (lane == 0) out[w] = p + lb[0];
    } else {
        *(float4*)&g_h[w * DIM + l4] = r;
    }
}

// ---------------- launch ----------------

extern "C" void kernel_launch(void* const* d_in, const int* in_sizes, int n_in,
                              void* d_out, int out_size) {
    const float* x  = (const float*)d_in[0];
    const int*   ei = (const int*)d_in[1];
    const int*   src = ei;
    const int*   dst = ei + EE;
    const float* W0 = (const float*)d_in[2];
    const float* b0 = (const float*)d_in[3];
    const float* W1 = (const float*)d_in[4];
    const float* b1 = (const float*)d_in[5];
    const float* W2 = (const float*)d_in[6];
    const float* b2 = (const float*)d_in[7];
    const float* lw = (const float*)d_in[8];
    const float* lb = (const float*)d_in[9];
    float* out = (float*)d_out;

    zero_k<<<NB, 256>>>();
    count_k<<<EE / 256, 256>>>(dst);
    dinv_k<<<NB, 256>>>();
    scan1_k<<<NB, 256>>>();
    scan2_k<<<1, 256>>>();
    scan3_k<<<NB, 256>>>();
    place_k<<<EE / 256, 256>>>(src, dst);

    dim3 gg(NN / 64, 2);
    const int AGG_BLOCKS = (NN * 32) / 256;  // one warp per node

    // layer 0
    gemm_k<false><<<gg, 256>>>(x, W0);
    agg_k<false><<<AGG_BLOCKS, 256>>>(b0, nullptr, nullptr, nullptr);
    // layer 1
    gemm_k<true><<<gg, 256>>>(nullptr, W1);
    agg_k<false><<<AGG_BLOCKS, 256>>>(b1, nullptr, nullptr, nullptr);
    // layer 2 + final linear fused
    gemm_k<true><<<gg, 256>>>(nullptr, W2);
    agg_k<true><<<AGG_BLOCKS, 256>>>(b2, lw, lb, out);
}

// round 3
// speedup vs baseline: 1.2194x; 1.2194x over previous
#include <cuda_runtime.h>
#include <cstdint>

#define NN 40000
#define EE 640000
#define DIM 128
#define NB 157   // ceil(40000/256)

// Scratch (static device globals — no allocation)
__device__ float g_hs[NN * DIM];   // (h_in @ W) * dinv[row]
__device__ float g_h[NN * DIM];    // layer output
__device__ float g_dinv[NN];
__device__ int   g_cnt[NN];
__device__ int   g_off[NN];
__device__ int   g_pos[NN];
__device__ int   g_ssrc[EE];       // edge srcs sorted by dst (CSR)
__device__ int   g_bsum[NB];
__device__ int   g_bbase[NB];

// ---------------- degree / CSR build ----------------

__global__ void zero_k() {
    int i = blockIdx.x * blockDim.x + threadIdx.x;
    if (i < NN) g_cnt[i] = 0;
}

__global__ void count_k(const int* __restrict__ dst) {
    int e = blockIdx.x * blockDim.x + threadIdx.x;
    if (e < EE) atomicAdd(&g_cnt[dst[e]], 1);
}

__global__ void dinv_k() {
    int i = blockIdx.x * blockDim.x + threadIdx.x;
    if (i < NN) g_dinv[i] = rsqrtf(1.0f + (float)g_cnt[i]);
}

__global__ void scan1_k() {
    __shared__ int s[256];
    int i = blockIdx.x * 256 + threadIdx.x;
    s[threadIdx.x] = (i < NN) ? g_cnt[i] : 0;
    __syncthreads();
    for (int o = 128; o > 0; o >>= 1) {
        if (threadIdx.x < o) s[threadIdx.x] += s[threadIdx.x + o];
        __syncthreads();
    }
    if (threadIdx.x == 0) g_bsum[blockIdx.x] = s[0];
}

__global__ void scan2_k() {
    __shared__ int s[256];
    int t = threadIdx.x;
    int v = (t < NB) ? g_bsum[t] : 0;
    s[t] = v;
    __syncthreads();
    for (int o = 1; o < 256; o <<= 1) {
        int add = (t >= o) ? s[t - o] : 0;
        __syncthreads();
        s[t] += add;
        __syncthreads();
    }
    if (t < NB) g_bbase[t] = s[t] - v;   // exclusive base per chunk
}

__global__ void scan3_k() {
    __shared__ int s[256];
    int t = threadIdx.x;
    int i = blockIdx.x * 256 + t;
    int v = (i < NN) ? g_cnt[i] : 0;
    s[t] = v;
    __syncthreads();
    for (int o = 1; o < 256; o <<= 1) {
        int add = (t >= o) ? s[t - o] : 0;
        __syncthreads();
        s[t] += add;
        __syncthreads();
    }
    if (i < NN) {
        int off = g_bbase[blockIdx.x] + s[t] - v;  // exclusive prefix
        g_off[i] = off;
        g_pos[i] = off;
    }
}

__global__ void place_k(const int* __restrict__ src, const int* __restrict__ dst) {
    int e = blockIdx.x * blockDim.x + threadIdx.x;
    if (e < EE) {
        int d = dst[e];
        int p = atomicAdd(&g_pos[d], 1);
        g_ssrc[p] = src[e];
    }
}

// ---------------- tf32 tensor-core GEMM: g_hs = (A @ W) * dinv[row] ----------------
// One 256-thread block per 128-row tile. W and the A tile staged in smem
// (tf32-converted, stride 132 floats -> conflict-free fragment LDS).
// mma.sync.aligned.m16n8k8.row.col.f32.tf32.tf32.f32

__device__ __forceinline__ uint32_t f2tf32(float f) {
    uint32_t r;
    asm("cvt.rna.tf32.f32 %0, %1;" : "=r"(r) : "f"(f));
    return r;
}

#define SM_STRIDE 132
#define GEMM_SMEM (2 * 128 * SM_STRIDE * 4)

template <bool FROM_H>
__global__ void gemm_tc(const float* __restrict__ Ax, const float* __restrict__ W) {
    const float* __restrict__ A = FROM_H ? (const float*)g_h : Ax;
    extern __shared__ uint32_t sm[];
    uint32_t* sA = sm;                    // [128][132]
    uint32_t* sW = sm + 128 * SM_STRIDE;  // [128][132]

    int tid = threadIdx.x;
    int r0 = blockIdx.x * 128;

    // Stage W: 128x128, tf32-converted
    #pragma unroll
    for (int i = tid; i < 128 * 32; i += 256) {
        int k = i >> 5, c4 = (i & 31) << 2;
        float4 v = *(const float4*)&W[k * DIM + c4];
        uint32_t* p = &sW[k * SM_STRIDE + c4];
        p[0] = f2tf32(v.x); p[1] = f2tf32(v.y); p[2] = f2tf32(v.z); p[3] = f2tf32(v.w);
    }
    // Stage A tile (clamp OOB rows; epilogue masks them)
    #pragma unroll
    for (int i = tid; i < 128 * 32; i += 256) {
        int r = i >> 5, c4 = (i & 31) << 2;
        int rr = min(r0 + r, NN - 1);
        float4 v = *(const float4*)&A[rr * DIM + c4];
        uint32_t* p = &sA[r * SM_STRIDE + c4];
        p[0] = f2tf32(v.x); p[1] = f2tf32(v.y); p[2] = f2tf32(v.z); p[3] = f2tf32(v.w);
    }
    __syncthreads();

    int warp = tid >> 5, lane = tid & 31;
    int g = lane >> 2, tg = lane & 3;
    int rbase = warp * 16;

    float c[16][4];
    #pragma unroll
    for (int nt = 0; nt < 16; nt++) {
        c[nt][0] = 0.f; c[nt][1] = 0.f; c[nt][2] = 0.f; c[nt][3] = 0.f;
    }

    #pragma unroll
    for (int kt = 0; kt < 16; kt++) {
        int k0 = kt * 8;
        uint32_t a0 = sA[(rbase + g) * SM_STRIDE + k0 + tg];
        uint32_t a1 = sA[(rbase + g + 8) * SM_STRIDE + k0 + tg];
        uint32_t a2 = sA[(rbase + g) * SM_STRIDE + k0 + tg + 4];
        uint32_t a3 = sA[(rbase + g + 8) * SM_STRIDE + k0 + tg + 4];
        #pragma unroll
        for (int nt = 0; nt < 16; nt++) {
            uint32_t b0 = sW[(k0 + tg) * SM_STRIDE + nt * 8 + g];
            uint32_t b1 = sW[(k0 + tg + 4) * SM_STRIDE + nt * 8 + g];
            asm volatile(
                "mma.sync.aligned.m16n8k8.row.col.f32.tf32.tf32.f32 "
                "{%0,%1,%2,%3}, {%4,%5,%6,%7}, {%8,%9}, {%0,%1,%2,%3};\n"
                : "+f"(c[nt][0]), "+f"(c[nt][1]), "+f"(c[nt][2]), "+f"(c[nt][3])
                : "r"(a0), "r"(a1), "r"(a2), "r"(a3), "r"(b0), "r"(b1));
        }
    }

    // Epilogue: scale by dinv[row], write g_hs
    int row0 = r0 + rbase + g;
    int row1 = row0 + 8;
    float d0 = (row0 < NN) ? g_dinv[row0] : 0.f;
    float d1 = (row1 < NN) ? g_dinv[row1] : 0.f;
    #pragma unroll
    for (int nt = 0; nt < 16; nt++) {
        int col = nt * 8 + 2 * tg;
        if (row0 < NN) {
            float2 o; o.x = c[nt][0] * d0; o.y = c[nt][1] * d0;
            *(float2*)&g_hs[row0 * DIM + col] = o;
        }
        if (row1 < NN) {
            float2 o; o.x = c[nt][2] * d1; o.y = c[nt][3] * d1;
            *(float2*)&g_hs[row1 * DIM + col] = o;
        }
    }
}

// ---------------- Aggregation: one warp per node ----------------
// h_out[i] = relu(dinv[i] * (sum_{s in N(i)} hs[s] + hs[i]) + b)
// FINAL: also out[i] = h_out[i] . lin_w + lin_b

template <bool FINAL>
__global__ void agg_k(const float* __restrict__ bias,
                      const float* __restrict__ lw,
                      const float* __restrict__ lb,
                      float* __restrict__ out) {
    int w = (blockIdx.x * blockDim.x + threadIdx.x) >> 5;
    int lane = threadIdx.x & 31;
    if (w >= NN) return;
    int l4 = lane * 4;

    float4 acc = make_float4(0.f, 0.f, 0.f, 0.f);
    int beg = g_off[w];
    int n = g_cnt[w];
    #pragma unroll 4
    for (int e = beg; e < beg + n; e++) {
        int s = g_ssrc[e];
        float4 v = *(const float4*)&g_hs[s * DIM + l4];
        acc.x += v.x; acc.y += v.y; acc.z += v.z; acc.w += v.w;
    }
    float4 self = *(const float4*)&g_hs[w * DIM + l4];
    float di = g_dinv[w];
    float4 bb = *(const float4*)&bias[l4];

    float4 r;
    r.x = fmaxf(di * (acc.x + self.x) + bb.x, 0.f);
    r.y = fmaxf(di * (acc.y + self.y) + bb.y, 0.f);
    r.z = fmaxf(di * (acc.z + self.z) + bb.z, 0.f);
    r.w = fmaxf(di * (acc.w + self.w) + bb.w, 0.f);

    if (FINAL) {
        float4 lwv = *(const float4*)&lw[l4];
        float p = r.x * lwv.x + r.y * lwv.y + r.z * lwv.z + r.w * lwv.w;
        #pragma unroll
        for (int o = 16; o > 0; o >>= 1) p += __shfl_xor_sync(0xffffffffu, p, o);
        if (lane == 0) out[w] = p + lb[0];
    } else {
        *(float4*)&g_h[w * DIM + l4] = r;
    }
}

// ---------------- launch ----------------

extern "C" void kernel_launch(void* const* d_in, const int* in_sizes, int n_in,
                              void* d_out, int out_size) {
    const float* x  = (const float*)d_in[0];
    const int*   ei = (const int*)d_in[1];
    const int*   src = ei;
    const int*   dst = ei + EE;
    const float* W0 = (const float*)d_in[2];
    const float* b0 = (const float*)d_in[3];
    const float* W1 = (const float*)d_in[4];
    const float* b1 = (const float*)d_in[5];
    const float* W2 = (const float*)d_in[6];
    const float* b2 = (const float*)d_in[7];
    const float* lw = (const float*)d_in[8];
    const float* lb = (const float*)d_in[9];
    float* out = (float*)d_out;

    cudaFuncSetAttribute(gemm_tc<false>, cudaFuncAttributeMaxDynamicSharedMemorySize, GEMM_SMEM);
    cudaFuncSetAttribute(gemm_tc<true>,  cudaFuncAttributeMaxDynamicSharedMemorySize, GEMM_SMEM);

    zero_k<<<NB, 256>>>();
    count_k<<<EE / 256, 256>>>(dst);
    dinv_k<<<NB, 256>>>();
    scan1_k<<<NB, 256>>>();
    scan2_k<<<1, 256>>>();
    scan3_k<<<NB, 256>>>();
    place_k<<<EE / 256, 256>>>(src, dst);

    const int GEMM_BLOCKS = (NN + 127) / 128;   // 313
    const int AGG_BLOCKS = (NN * 32) / 256;     // one warp per node

    // layer 0
    gemm_tc<false><<<GEMM_BLOCKS, 256, GEMM_SMEM>>>(x, W0);
    agg_k<false><<<AGG_BLOCKS, 256>>>(b0, nullptr, nullptr, nullptr);
    // layer 1
    gemm_tc<true><<<GEMM_BLOCKS, 256, GEMM_SMEM>>>(nullptr, W1);
    agg_k<false><<<AGG_BLOCKS, 256>>>(b1, nullptr, nullptr, nullptr);
    // layer 2 + final linear fused
    gemm_tc<true><<<GEMM_BLOCKS, 256, GEMM_SMEM>>>(nullptr, W2);
    agg_k<true><<<AGG_BLOCKS, 256>>>(b2, lw, lb, out);
}